// round 1
// baseline (speedup 1.0000x reference)
#include <cuda_runtime.h>
#include <math_constants.h>
#include <cstdint>

// ============================================================================
// RuleModel forward = pure index network:
//   gate(w,g) one-hot at argmax_i(w[i,j]+g[i,j])  =>  h@gate = column gather.
// Phase 1: column argmax of w+g for 12 gate matrices (atomicMax on packed key)
// Phase 2: per-row gather network in shared memory, fused final dot product.
// ============================================================================

#define N_GATES 12
#define CHUNK 128          // rows per argmax partial block
#define RPB 8              // rows per eval block
#define NT 1024            // eval threads per block
#define NFEAT 5122
#define NFEAT_PAD 5128     // round up to multiple of 8 for swizzle
#define EVAL_SMEM (NFEAT_PAD * RPB * 4)

__device__ unsigned long long g_keys[N_GATES * 1024];
__device__ int g_idx[N_GATES * 1024];

struct AmDesc {
  const float* w[N_GATES];
  const float* g[N_GATES];
  int din[N_GATES];
  int dout[N_GATES];
  int colTiles[N_GATES];
  int jobEnd[N_GATES];
};

__device__ __forceinline__ unsigned sortable(float f) {
  unsigned u = __float_as_uint(f);
  return (u & 0x80000000u) ? ~u : (u | 0x80000000u);
}

__global__ void zero_keys_kernel() {
  int i = blockIdx.x * blockDim.x + threadIdx.x;
  if (i < N_GATES * 1024) g_keys[i] = 0ull;
}

__global__ void argmax_partial_kernel(AmDesc d) {
  int job = blockIdx.x;
  int gi = 0;
  while (gi < N_GATES - 1 && job >= d.jobEnd[gi]) gi++;
  int base = gi ? d.jobEnd[gi - 1] : 0;
  int local = job - base;
  int ct = d.colTiles[gi];
  int rowChunk = local / ct;
  int colTile = local - rowChunk * ct;
  int dout = d.dout[gi];
  int col = colTile * 256 + threadIdx.x;
  const float* __restrict__ wp = d.w[gi] + col;
  const float* __restrict__ gp = d.g[gi] + col;
  int r0 = rowChunk * CHUNK;
  int r1 = min(r0 + CHUNK, d.din[gi]);
  float best = -CUDART_INF_F;
  int bi = r0;
#pragma unroll 4
  for (int r = r0; r < r1; r++) {
    float v = __ldg(wp + (long)r * dout) + __ldg(gp + (long)r * dout);
    if (v > best) { best = v; bi = r; }  // strict '>' keeps first index (JAX tie rule)
  }
  // pack: higher value wins; on equal value, SMALLER index wins (inverted low bits)
  unsigned long long key =
      ((unsigned long long)sortable(best) << 32) |
      (unsigned long long)(0xFFFFFFFFu - (unsigned)bi);
  atomicMax(&g_keys[gi * 1024 + col], key);
}

__global__ void extract_kernel() {
  int i = blockIdx.x * blockDim.x + threadIdx.x;
  if (i < N_GATES * 1024)
    g_idx[i] = (int)(0xFFFFFFFFu - (unsigned)(g_keys[i] & 0xFFFFFFFFull));
}

// ---------------- eval ----------------
// smem layout: transposed h[feat][RPB] with XOR swizzle over 16B bank-groups.
// float index of the float4 holding rows grp*4..grp*4+3 of feature `feat`:
__device__ __forceinline__ int sidx4(int feat, int grp) {
  return (feat * 8 + grp * 4) ^ ((feat & 7) << 2);
}
__device__ __forceinline__ int sidx1(int feat, int r) {
  return sidx4(feat, r >> 2) + (r & 3);
}

__device__ __forceinline__ float4 gate_op(float4 va, float4 vb, int isOr) {
  float4 o;
  if (!isOr) {
    o.x = va.x * vb.x; o.y = va.y * vb.y; o.z = va.z * vb.z; o.w = va.w * vb.w;
  } else {
    o.x = 1.0f - (1.0f - va.x) * (1.0f - vb.x);
    o.y = 1.0f - (1.0f - va.y) * (1.0f - vb.y);
    o.z = 1.0f - (1.0f - va.z) * (1.0f - vb.z);
    o.w = 1.0f - (1.0f - va.w) * (1.0f - vb.w);
  }
  return o;
}

__global__ __launch_bounds__(NT, 1) void eval_kernel(
    const float* __restrict__ x,
    const float* __restrict__ lin_w,
    float* __restrict__ out) {
  extern __shared__ float sm[];
  const int tid = threadIdx.x;
  const long row0 = (long)blockIdx.x * RPB;

  // build h1 = [x, 1-x, 1, 0]  (features 0..1025)
  for (int i = tid; i < 512 * RPB; i += NT) {
    int r = i >> 9, c = i & 511;
    float v = __ldg(x + (row0 + r) * 512 + c);
    sm[sidx1(c, r)] = v;
    sm[sidx1(512 + c, r)] = 1.0f - v;
  }
  if (tid < RPB) {
    sm[sidx1(1024, tid)] = 1.0f;
    sm[sidx1(1025, tid)] = 0.0f;
  }
  __syncthreads();

  // layers 1 & 2: compute c,d gates, append to h
#pragma unroll
  for (int l = 0; l < 2; l++) {
    const int nout = 1024;
    const int obase = (l == 0) ? 1026 : 3074;
    const int* __restrict__ ic1 = g_idx + (4 * l + 0) * 1024;
    const int* __restrict__ ic2 = g_idx + (4 * l + 1) * 1024;
    const int* __restrict__ id1 = g_idx + (4 * l + 2) * 1024;
    const int* __restrict__ id2 = g_idx + (4 * l + 3) * 1024;
#pragma unroll 2
    for (int item = tid; item < nout * 4; item += NT) {
      int grp = item & 1;
      int t2 = item >> 1;
      int isOr = (t2 >= nout);
      int j = t2 - (isOr ? nout : 0);
      int a = __ldg((isOr ? id1 : ic1) + j);
      int b = __ldg((isOr ? id2 : ic2) + j);
      float4 va = *(const float4*)(sm + sidx4(a, grp));
      float4 vb = *(const float4*)(sm + sidx4(b, grp));
      float4 o = gate_op(va, vb, isOr);
      *(float4*)(sm + sidx4(obase + t2, grp)) = o;  // c at obase+j, d at obase+nout+j
    }
    __syncthreads();
  }

  // layer 3 fused with lin_w dot product
  {
    const int nout = 512;
    const int* __restrict__ ic1 = g_idx + 8 * 1024;
    const int* __restrict__ ic2 = g_idx + 9 * 1024;
    const int* __restrict__ id1 = g_idx + 10 * 1024;
    const int* __restrict__ id2 = g_idx + 11 * 1024;
    float4 acc = make_float4(0.f, 0.f, 0.f, 0.f);
#pragma unroll 2
    for (int item = tid; item < nout * 4; item += NT) {
      int grp = item & 1;  // == tid&1 always (NT even)
      int t2 = item >> 1;
      int isOr = (t2 >= nout);
      int j = t2 - (isOr ? nout : 0);
      int a = __ldg((isOr ? id1 : ic1) + j);
      int b = __ldg((isOr ? id2 : ic2) + j);
      float w = __ldg(lin_w + (isOr ? 512 : 0) + j);
      float4 va = *(const float4*)(sm + sidx4(a, grp));
      float4 vb = *(const float4*)(sm + sidx4(b, grp));
      float4 o = gate_op(va, vb, isOr);
      acc.x += w * o.x; acc.y += w * o.y; acc.z += w * o.z; acc.w += w * o.w;
    }
    __syncthreads();  // all gathers done; safe to reuse sm

    float4* red = (float4*)sm;
    red[tid] = acc;
    __syncthreads();
    int half = tid >> 1;
    int grp = tid & 1;
    for (int s = NT / 4; s >= 1; s >>= 1) {
      if (half < s) {
        float4 aa = red[half * 2 + grp];
        float4 bb = red[(half + s) * 2 + grp];
        aa.x += bb.x; aa.y += bb.y; aa.z += bb.z; aa.w += bb.w;
        red[half * 2 + grp] = aa;
      }
      __syncthreads();
    }
    if (tid < 2) {
      float4 v = red[tid];  // tid==grp: rows grp*4 .. grp*4+3
      out[row0 + tid * 4 + 0] = v.x;
      out[row0 + tid * 4 + 1] = v.y;
      out[row0 + tid * 4 + 2] = v.z;
      out[row0 + tid * 4 + 3] = v.w;
    }
  }
}

// ============================================================================

extern "C" void kernel_launch(void* const* d_in, const int* in_sizes, int n_in,
                              void* d_out, int out_size) {
  // Identify inputs by element count (robust to metadata ordering):
  //   l1 group: 1026*1024, l2: 3074*1024, l3: 5122*512 (8 consecutive matrices
  //   each, order wc1,wc2,wd1,wd2,gc1,gc2,gd1,gd2), x: 32768*512, lin_w: 1024.
  const int S_L[3] = {1026 * 1024, 3074 * 1024, 5122 * 512};
  int lstart[3] = {-1, -1, -1};
  int xi = -1, lwi = -1;
  for (int i = 0; i < n_in; i++) {
    int s = in_sizes[i];
    if (s == 32768 * 512) { if (xi < 0) xi = i; }
    else if (s == 1024) { if (lwi < 0) lwi = i; }
    else {
      for (int l = 0; l < 3; l++)
        if (s == S_L[l] && lstart[l] < 0) { lstart[l] = i; break; }
    }
  }

  AmDesc d;
  const int din[3] = {1026, 3074, 5122};
  const int dout[3] = {1024, 1024, 512};
  int cum = 0;
  for (int l = 0; l < 3; l++) {
    for (int t = 0; t < 4; t++) {
      int gi = l * 4 + t;
      d.w[gi] = (const float*)d_in[lstart[l] + t];
      d.g[gi] = (const float*)d_in[lstart[l] + 4 + t];
      d.din[gi] = din[l];
      d.dout[gi] = dout[l];
      int ct = dout[l] / 256;
      d.colTiles[gi] = ct;
      int rc = (din[l] + CHUNK - 1) / CHUNK;
      cum += rc * ct;
      d.jobEnd[gi] = cum;
    }
  }

  zero_keys_kernel<<<(N_GATES * 1024 + 255) / 256, 256>>>();
  argmax_partial_kernel<<<cum, 256>>>(d);
  extract_kernel<<<(N_GATES * 1024 + 255) / 256, 256>>>();

  cudaFuncSetAttribute(eval_kernel, cudaFuncAttributeMaxDynamicSharedMemorySize,
                       EVAL_SMEM);
  eval_kernel<<<32768 / RPB, NT, EVAL_SMEM>>>(
      (const float*)d_in[xi], (const float*)d_in[lwi], (float*)d_out);
}

// round 2
// speedup vs baseline: 1.6480x; 1.6480x over previous
#include <cuda_runtime.h>
#include <cuda_fp16.h>
#include <math_constants.h>
#include <cstdint>

// ============================================================================
// RuleModel forward = pure index network:
//   gate(w,g) one-hot at argmax_i(w[i,j]+g[i,j])  =>  h@gate = column gather.
// Phase 1: column argmax of w+g for 12 gate matrices (atomicMax on packed key)
// Phase 2: per-row gather network in shared memory (h stored fp16, 8 rows
//          packed into 16B per feature -> one LDS.128 per operand), fused
//          final dot product.
// ============================================================================

#define N_GATES 12
#define CHUNK 128          // rows per argmax partial block
#define RPB 8              // rows per eval block (8 halves = 16B per feature)
#define NT 1024            // eval threads per block
#define NFEAT_PAD 5128
#define EVAL_SMEM (NFEAT_PAD * RPB * 2 + 1024)

__device__ unsigned long long g_keys[N_GATES * 1024];
__device__ int g_idx[N_GATES * 1024];

struct AmDesc {
  const float* w[N_GATES];
  const float* g[N_GATES];
  int din[N_GATES];
  int dout[N_GATES];
  int colTiles[N_GATES];
  int jobEnd[N_GATES];
};

__device__ __forceinline__ unsigned sortable(float f) {
  unsigned u = __float_as_uint(f);
  return (u & 0x80000000u) ? ~u : (u | 0x80000000u);
}

__global__ void zero_keys_kernel() {
  int i = blockIdx.x * blockDim.x + threadIdx.x;
  if (i < N_GATES * 1024) g_keys[i] = 0ull;
}

__global__ void argmax_partial_kernel(AmDesc d) {
  int job = blockIdx.x;
  int gi = 0;
  while (gi < N_GATES - 1 && job >= d.jobEnd[gi]) gi++;
  int base = gi ? d.jobEnd[gi - 1] : 0;
  int local = job - base;
  int ct = d.colTiles[gi];
  int rowChunk = local / ct;
  int colTile = local - rowChunk * ct;
  int dout = d.dout[gi];
  int col = colTile * 256 + threadIdx.x;
  const float* __restrict__ wp = d.w[gi] + col;
  const float* __restrict__ gp = d.g[gi] + col;
  int r0 = rowChunk * CHUNK;
  int r1 = min(r0 + CHUNK, d.din[gi]);
  float best = -CUDART_INF_F;
  int bi = r0;
#pragma unroll 4
  for (int r = r0; r < r1; r++) {
    float v = __ldg(wp + (long)r * dout) + __ldg(gp + (long)r * dout);
    if (v > best) { best = v; bi = r; }  // strict '>' keeps first index (JAX tie rule)
  }
  unsigned long long key =
      ((unsigned long long)sortable(best) << 32) |
      (unsigned long long)(0xFFFFFFFFu - (unsigned)bi);
  atomicMax(&g_keys[gi * 1024 + col], key);
}

__global__ void extract_kernel() {
  int i = blockIdx.x * blockDim.x + threadIdx.x;
  if (i < N_GATES * 1024)
    g_idx[i] = (int)(0xFFFFFFFFu - (unsigned)(g_keys[i] & 0xFFFFFFFFull));
}

// ---------------- eval ----------------
// h stored transposed: feature f -> 8 halves (rows 0..7) at sm_h[f*8 .. f*8+7]
// One float4 load gives all 8 rows of a feature.

struct H8 { __half2 p0, p1, p2, p3; };

__device__ __forceinline__ H8 ld_feat(const float* sm, int f) {
  float4 v = *(const float4*)(sm + f * 4);
  H8 h;
  h.p0 = *(__half2*)&v.x; h.p1 = *(__half2*)&v.y;
  h.p2 = *(__half2*)&v.z; h.p3 = *(__half2*)&v.w;
  return h;
}
__device__ __forceinline__ void st_feat(float* sm, int f, H8 h) {
  float4 v;
  *(__half2*)&v.x = h.p0; *(__half2*)&v.y = h.p1;
  *(__half2*)&v.z = h.p2; *(__half2*)&v.w = h.p3;
  *(float4*)(sm + f * 4) = v;
}

__device__ __forceinline__ H8 gate_op(H8 a, H8 b, int isOr) {
  H8 o;
  if (!isOr) {
    o.p0 = __hmul2(a.p0, b.p0); o.p1 = __hmul2(a.p1, b.p1);
    o.p2 = __hmul2(a.p2, b.p2); o.p3 = __hmul2(a.p3, b.p3);
  } else {
    const __half2 one = __float2half2_rn(1.0f);
    // OR: a + b*(1-a)
    o.p0 = __hfma2(b.p0, __hsub2(one, a.p0), a.p0);
    o.p1 = __hfma2(b.p1, __hsub2(one, a.p1), a.p1);
    o.p2 = __hfma2(b.p2, __hsub2(one, a.p2), a.p2);
    o.p3 = __hfma2(b.p3, __hsub2(one, a.p3), a.p3);
  }
  return o;
}

__global__ __launch_bounds__(NT, 2) void eval_kernel(
    const float* __restrict__ x,
    const float* __restrict__ lin_w,
    float* __restrict__ out) {
  extern __shared__ float sm[];
  __half* sm_h = (__half*)sm;
  float* sm_red = sm + NFEAT_PAD * RPB / 2;  // 1KB reduction scratch
  const int tid = threadIdx.x;
  const long row0 = (long)blockIdx.x * RPB;

  // build h1 = [x, 1-x, 1, 0]  (features 0..1025)
  for (int i = tid; i < 512 * RPB; i += NT) {
    int r = i >> 9, c = i & 511;
    float v = __ldg(x + (row0 + r) * 512 + c);
    sm_h[c * 8 + r] = __float2half_rn(v);
    sm_h[(512 + c) * 8 + r] = __float2half_rn(1.0f - v);
  }
  if (tid < RPB) {
    sm_h[1024 * 8 + tid] = __float2half_rn(1.0f);
    sm_h[1025 * 8 + tid] = __float2half_rn(0.0f);
  }
  __syncthreads();

  // layers 1 & 2: 2048 gate outputs each (1024 AND then 1024 OR)
#pragma unroll
  for (int l = 0; l < 2; l++) {
    const int obase = (l == 0) ? 1026 : 3074;
    const int* __restrict__ ib = g_idx + 4 * l * 1024;
#pragma unroll 2
    for (int t = tid; t < 2048; t += NT) {
      int isOr = t >> 10;
      int j = t & 1023;
      int a = __ldg(ib + (isOr ? 2 : 0) * 1024 + j);
      int b = __ldg(ib + (isOr ? 3 : 1) * 1024 + j);
      H8 va = ld_feat(sm, a);
      H8 vb = ld_feat(sm, b);
      st_feat(sm, obase + t, gate_op(va, vb, isOr));
    }
    __syncthreads();
  }

  // layer 3 (512 AND + 512 OR) fused with lin_w dot product
  {
    const int* __restrict__ ib = g_idx + 8 * 1024;
    float acc[8];
#pragma unroll
    for (int k = 0; k < 8; k++) acc[k] = 0.0f;
#pragma unroll
    for (int t = tid; t < 1024; t += NT) {  // single trip at NT=1024
      int isOr = t >> 9;
      int j = t & 511;
      int a = __ldg(ib + (isOr ? 2 : 0) * 1024 + j);
      int b = __ldg(ib + (isOr ? 3 : 1) * 1024 + j);
      float w = __ldg(lin_w + isOr * 512 + j);
      H8 va = ld_feat(sm, a);
      H8 vb = ld_feat(sm, b);
      H8 o = gate_op(va, vb, isOr);
      float2 f0 = __half22float2(o.p0);
      float2 f1 = __half22float2(o.p1);
      float2 f2 = __half22float2(o.p2);
      float2 f3 = __half22float2(o.p3);
      acc[0] += w * f0.x; acc[1] += w * f0.y;
      acc[2] += w * f1.x; acc[3] += w * f1.y;
      acc[4] += w * f2.x; acc[5] += w * f2.y;
      acc[6] += w * f3.x; acc[7] += w * f3.y;
    }
    // warp reduce
#pragma unroll
    for (int off = 16; off; off >>= 1)
#pragma unroll
      for (int k = 0; k < 8; k++)
        acc[k] += __shfl_down_sync(0xffffffffu, acc[k], off);
    int warp = tid >> 5, lane = tid & 31;
    if (lane == 0)
#pragma unroll
      for (int k = 0; k < 8; k++) sm_red[warp * 8 + k] = acc[k];
    __syncthreads();
    if (tid < 8) {
      float s = 0.0f;
#pragma unroll
      for (int w = 0; w < NT / 32; w++) s += sm_red[w * 8 + tid];
      out[row0 + tid] = s;
    }
  }
}

// ============================================================================

extern "C" void kernel_launch(void* const* d_in, const int* in_sizes, int n_in,
                              void* d_out, int out_size) {
  // Identify inputs by element count (robust to metadata ordering).
  const int S_L[3] = {1026 * 1024, 3074 * 1024, 5122 * 512};
  int lstart[3] = {-1, -1, -1};
  int xi = -1, lwi = -1;
  for (int i = 0; i < n_in; i++) {
    int s = in_sizes[i];
    if (s == 32768 * 512) { if (xi < 0) xi = i; }
    else if (s == 1024) { if (lwi < 0) lwi = i; }
    else {
      for (int l = 0; l < 3; l++)
        if (s == S_L[l] && lstart[l] < 0) { lstart[l] = i; break; }
    }
  }

  AmDesc d;
  const int din[3] = {1026, 3074, 5122};
  const int dout[3] = {1024, 1024, 512};
  int cum = 0;
  for (int l = 0; l < 3; l++) {
    for (int t = 0; t < 4; t++) {
      int gi = l * 4 + t;
      d.w[gi] = (const float*)d_in[lstart[l] + t];
      d.g[gi] = (const float*)d_in[lstart[l] + 4 + t];
      d.din[gi] = din[l];
      d.dout[gi] = dout[l];
      int ct = dout[l] / 256;
      d.colTiles[gi] = ct;
      int rc = (din[l] + CHUNK - 1) / CHUNK;
      cum += rc * ct;
      d.jobEnd[gi] = cum;
    }
  }

  zero_keys_kernel<<<(N_GATES * 1024 + 255) / 256, 256>>>();
  argmax_partial_kernel<<<cum, 256>>>(d);
  extract_kernel<<<(N_GATES * 1024 + 255) / 256, 256>>>();

  cudaFuncSetAttribute(eval_kernel, cudaFuncAttributeMaxDynamicSharedMemorySize,
                       EVAL_SMEM);
  eval_kernel<<<32768 / RPB, NT, EVAL_SMEM>>>(
      (const float*)d_in[xi], (const float*)d_in[lwi], (float*)d_out);
}

// round 3
// speedup vs baseline: 1.9246x; 1.1678x over previous
#include <cuda_runtime.h>
#include <cuda_fp16.h>
#include <math_constants.h>
#include <cstdint>

// ============================================================================
// RuleModel forward = pure index network (gumbel-softmax hard gate => gather).
// Phase 1: column argmax of w+g for 12 gate matrices (atomicMax packed key)
// Phase 1b: dead-gate elimination: only gates whose output feature is
//           (transitively) referenced by the final layer are computed.
//           Compacted gate lists (a, b, dest, isOr) built on device.
// Phase 2: per-row gather network in fp16 shared memory (8 rows = 16B/feature,
//          one LDS.128 per operand), fused final dot product.
// ============================================================================

#define N_GATES 12
#define CHUNK 128
#define RPB 8
#define NT 1024
#define NFEAT_PAD 5128
#define EVAL_SMEM (NFEAT_PAD * RPB * 2 + 1024)

__device__ unsigned long long g_keys[N_GATES * 1024];
__device__ int g_idx[N_GATES * 1024];
__device__ int g_featLive[5122];
__device__ int g_cnt[2];              // [0]=layer1 live count, [1]=layer2
__device__ int4 g_list1[2048];        // (a, b, dest, isOr)
__device__ int4 g_list2[2048];

struct AmDesc {
  const float* w[N_GATES];
  const float* g[N_GATES];
  int din[N_GATES];
  int dout[N_GATES];
  int colTiles[N_GATES];
  int jobEnd[N_GATES];
};

__device__ __forceinline__ unsigned sortable(float f) {
  unsigned u = __float_as_uint(f);
  return (u & 0x80000000u) ? ~u : (u | 0x80000000u);
}

__global__ void zero_keys_kernel() {
  int i = blockIdx.x * blockDim.x + threadIdx.x;
  if (i < N_GATES * 1024) g_keys[i] = 0ull;
  if (i < 5122) g_featLive[i] = 0;
  if (i < 2) g_cnt[i] = 0;
}

__global__ void argmax_partial_kernel(AmDesc d) {
  int job = blockIdx.x;
  int gi = 0;
  while (gi < N_GATES - 1 && job >= d.jobEnd[gi]) gi++;
  int base = gi ? d.jobEnd[gi - 1] : 0;
  int local = job - base;
  int ct = d.colTiles[gi];
  int rowChunk = local / ct;
  int colTile = local - rowChunk * ct;
  int dout = d.dout[gi];
  int col = colTile * 256 + threadIdx.x;
  const float* __restrict__ wp = d.w[gi] + col;
  const float* __restrict__ gp = d.g[gi] + col;
  int r0 = rowChunk * CHUNK;
  int r1 = min(r0 + CHUNK, d.din[gi]);
  float best = -CUDART_INF_F;
  int bi = r0;
#pragma unroll 4
  for (int r = r0; r < r1; r++) {
    float v = __ldg(wp + (long)r * dout) + __ldg(gp + (long)r * dout);
    if (v > best) { best = v; bi = r; }  // strict '>': first index on ties
  }
  unsigned long long key =
      ((unsigned long long)sortable(best) << 32) |
      (unsigned long long)(0xFFFFFFFFu - (unsigned)bi);
  atomicMax(&g_keys[gi * 1024 + col], key);
}

__global__ void extract_kernel() {
  int i = blockIdx.x * blockDim.x + threadIdx.x;
  if (i < N_GATES * 1024)
    g_idx[i] = (int)(0xFFFFFFFFu - (unsigned)(g_keys[i] & 0xFFFFFFFFull));
}

// ---- liveness pass ----
// K1: mark features read by layer 3 (all its 1024 gates are live).
__global__ void live3_kernel() {
  int i = blockIdx.x * blockDim.x + threadIdx.x;  // 2048 index slots
  if (i < 2048) {
    int arr = i >> 9;          // 0..3 (ic1, ic2, id1, id2)
    int j = i & 511;
    int idx = g_idx[(8 + arr) * 1024 + j];
    g_featLive[idx] = 1;
  }
}
// K2: layer-2 gate t live iff feature 3074+t referenced; emit + mark its inputs.
__global__ void live2_kernel() {
  int t = blockIdx.x * blockDim.x + threadIdx.x;  // 0..2047
  if (t < 2048 && g_featLive[3074 + t]) {
    int isOr = t >> 10;
    int j = t & 1023;
    int a = g_idx[(4 + (isOr ? 2 : 0)) * 1024 + j];
    int b = g_idx[(4 + (isOr ? 3 : 1)) * 1024 + j];
    g_featLive[a] = 1;
    g_featLive[b] = 1;
    int p = atomicAdd(&g_cnt[1], 1);
    g_list2[p] = make_int4(a, b, 3074 + t, isOr);
  }
}
// K3: layer-1 gate t live iff feature 1026+t referenced (by l3 or live l2).
__global__ void live1_kernel() {
  int t = blockIdx.x * blockDim.x + threadIdx.x;
  if (t < 2048 && g_featLive[1026 + t]) {
    int isOr = t >> 10;
    int j = t & 1023;
    int a = g_idx[(isOr ? 2 : 0) * 1024 + j];
    int b = g_idx[(isOr ? 3 : 1) * 1024 + j];
    int p = atomicAdd(&g_cnt[0], 1);
    g_list1[p] = make_int4(a, b, 1026 + t, isOr);
  }
}

// ---------------- eval ----------------
// h transposed: feature f -> 8 halves (rows 0..7) at 16B granule sm + f*4.

struct H8 { __half2 p0, p1, p2, p3; };

__device__ __forceinline__ H8 ld_feat(const float* sm, int f) {
  float4 v = *(const float4*)(sm + f * 4);
  H8 h;
  h.p0 = *(__half2*)&v.x; h.p1 = *(__half2*)&v.y;
  h.p2 = *(__half2*)&v.z; h.p3 = *(__half2*)&v.w;
  return h;
}
__device__ __forceinline__ void st_feat(float* sm, int f, H8 h) {
  float4 v;
  *(__half2*)&v.x = h.p0; *(__half2*)&v.y = h.p1;
  *(__half2*)&v.z = h.p2; *(__half2*)&v.w = h.p3;
  *(float4*)(sm + f * 4) = v;
}

__device__ __forceinline__ H8 gate_op(H8 a, H8 b, int isOr) {
  H8 o;
  if (!isOr) {
    o.p0 = __hmul2(a.p0, b.p0); o.p1 = __hmul2(a.p1, b.p1);
    o.p2 = __hmul2(a.p2, b.p2); o.p3 = __hmul2(a.p3, b.p3);
  } else {
    const __half2 one = __float2half2_rn(1.0f);
    o.p0 = __hfma2(b.p0, __hsub2(one, a.p0), a.p0);
    o.p1 = __hfma2(b.p1, __hsub2(one, a.p1), a.p1);
    o.p2 = __hfma2(b.p2, __hsub2(one, a.p2), a.p2);
    o.p3 = __hfma2(b.p3, __hsub2(one, a.p3), a.p3);
  }
  return o;
}

__global__ __launch_bounds__(NT, 2) void eval_kernel(
    const float* __restrict__ x,
    const float* __restrict__ lin_w,
    float* __restrict__ out) {
  extern __shared__ float sm[];
  __half* sm_h = (__half*)sm;
  float* sm_red = sm + NFEAT_PAD * RPB / 2;
  const int tid = threadIdx.x;
  const long row0 = (long)blockIdx.x * RPB;

  const int n1 = g_cnt[0];
  const int n2 = g_cnt[1];

  // ---- build h1 = [x, 1-x, 1, 0] via staged transpose ----
  // stage 8 rows x 512 floats (16KB) coalesced into scratch region
  // (float offset 12296 = feature 3074's slot; overwritten only in layer 2)
  {
    float* stg = sm + 12296;
    const float4* xg = (const float4*)(x + row0 * 512);
    ((float4*)stg)[tid] = __ldg(xg + tid);  // 1024 x 16B = 16KB
    __syncthreads();
    int c = tid & 511;
    int neg = tid >> 9;
    H8 h;
    float2 f;
#pragma unroll
    for (int p = 0; p < 4; p++) {
      f.x = stg[(2 * p + 0) * 512 + c];
      f.y = stg[(2 * p + 1) * 512 + c];
      if (neg) { f.x = 1.0f - f.x; f.y = 1.0f - f.y; }
      __half2 hv = __floats2half2_rn(f.x, f.y);
      if (p == 0) h.p0 = hv; else if (p == 1) h.p1 = hv;
      else if (p == 2) h.p2 = hv; else h.p3 = hv;
    }
    st_feat(sm, neg * 512 + c, h);
    if (tid < RPB) {
      sm_h[1024 * 8 + tid] = __float2half_rn(1.0f);
      sm_h[1025 * 8 + tid] = __float2half_rn(0.0f);
    }
    __syncthreads();
  }

  // ---- layer 1 (live gates only) ----
  for (int t = tid; t < n1; t += NT) {
    int4 e = __ldg((const int4*)g_list1 + t);
    H8 va = ld_feat(sm, e.x);
    H8 vb = ld_feat(sm, e.y);
    st_feat(sm, e.z, gate_op(va, vb, e.w));
  }
  __syncthreads();

  // ---- layer 2 (live gates only) ----
  for (int t = tid; t < n2; t += NT) {
    int4 e = __ldg((const int4*)g_list2 + t);
    H8 va = ld_feat(sm, e.x);
    H8 vb = ld_feat(sm, e.y);
    st_feat(sm, e.z, gate_op(va, vb, e.w));
  }
  __syncthreads();

  // ---- layer 3 fused with lin_w dot ----
  {
    const int* __restrict__ ib = g_idx + 8 * 1024;
    float acc[8];
#pragma unroll
    for (int k = 0; k < 8; k++) acc[k] = 0.0f;
    {
      int t = tid;  // single trip (1024 items, NT=1024)
      int isOr = t >> 9;
      int j = t & 511;
      int a = __ldg(ib + (isOr ? 2 : 0) * 1024 + j);
      int b = __ldg(ib + (isOr ? 3 : 1) * 1024 + j);
      float w = __ldg(lin_w + isOr * 512 + j);
      H8 va = ld_feat(sm, a);
      H8 vb = ld_feat(sm, b);
      H8 o = gate_op(va, vb, isOr);
      float2 f0 = __half22float2(o.p0);
      float2 f1 = __half22float2(o.p1);
      float2 f2 = __half22float2(o.p2);
      float2 f3 = __half22float2(o.p3);
      acc[0] += w * f0.x; acc[1] += w * f0.y;
      acc[2] += w * f1.x; acc[3] += w * f1.y;
      acc[4] += w * f2.x; acc[5] += w * f2.y;
      acc[6] += w * f3.x; acc[7] += w * f3.y;
    }
#pragma unroll
    for (int off = 16; off; off >>= 1)
#pragma unroll
      for (int k = 0; k < 8; k++)
        acc[k] += __shfl_down_sync(0xffffffffu, acc[k], off);
    int warp = tid >> 5, lane = tid & 31;
    if (lane == 0)
#pragma unroll
      for (int k = 0; k < 8; k++) sm_red[warp * 8 + k] = acc[k];
    __syncthreads();
    if (tid < 8) {
      float s = 0.0f;
#pragma unroll
      for (int w = 0; w < NT / 32; w++) s += sm_red[w * 8 + tid];
      out[row0 + tid] = s;
    }
  }
}

// ============================================================================

extern "C" void kernel_launch(void* const* d_in, const int* in_sizes, int n_in,
                              void* d_out, int out_size) {
  const int S_L[3] = {1026 * 1024, 3074 * 1024, 5122 * 512};
  int lstart[3] = {-1, -1, -1};
  int xi = -1, lwi = -1;
  for (int i = 0; i < n_in; i++) {
    int s = in_sizes[i];
    if (s == 32768 * 512) { if (xi < 0) xi = i; }
    else if (s == 1024) { if (lwi < 0) lwi = i; }
    else {
      for (int l = 0; l < 3; l++)
        if (s == S_L[l] && lstart[l] < 0) { lstart[l] = i; break; }
    }
  }

  AmDesc d;
  const int din[3] = {1026, 3074, 5122};
  const int dout[3] = {1024, 1024, 512};
  int cum = 0;
  for (int l = 0; l < 3; l++) {
    for (int t = 0; t < 4; t++) {
      int gi = l * 4 + t;
      d.w[gi] = (const float*)d_in[lstart[l] + t];
      d.g[gi] = (const float*)d_in[lstart[l] + 4 + t];
      d.din[gi] = din[l];
      d.dout[gi] = dout[l];
      int ct = dout[l] / 256;
      d.colTiles[gi] = ct;
      int rc = (din[l] + CHUNK - 1) / CHUNK;
      cum += rc * ct;
      d.jobEnd[gi] = cum;
    }
  }

  zero_keys_kernel<<<(N_GATES * 1024 + 255) / 256, 256>>>();
  argmax_partial_kernel<<<cum, 256>>>(d);
  extract_kernel<<<(N_GATES * 1024 + 255) / 256, 256>>>();
  live3_kernel<<<8, 256>>>();
  live2_kernel<<<8, 256>>>();
  live1_kernel<<<8, 256>>>();

  cudaFuncSetAttribute(eval_kernel, cudaFuncAttributeMaxDynamicSharedMemorySize,
                       EVAL_SMEM);
  eval_kernel<<<32768 / RPB, NT, EVAL_SMEM>>>(
      (const float*)d_in[xi], (const float*)d_in[lwi], (float*)d_out);
}

// round 5
// speedup vs baseline: 1.9603x; 1.0186x over previous
#include <cuda_runtime.h>
#include <cuda_fp16.h>
#include <math_constants.h>
#include <cstdint>

// ============================================================================
// RuleModel forward = pure index network (gumbel-softmax hard gate => gather).
// K1 argmax_partial: column argmax of w+g for 12 gate matrices (atomicMax key)
// K2 finalize (single block): extract indices, self-clean keys, transitive
//    dead-gate elimination, deterministic t-ordered compacted gate lists.
// K3 eval: per-row gather network in fp16 shared memory (8 rows = 16B/feature,
//    one LDS.128 per operand), fused final dot product.
// ============================================================================

#define N_GATES 12
#define CHUNK 128
#define RPB 8
#define NT 1024
#define FNT 1024
#define NFEAT_PAD 5128
#define EVAL_SMEM (NFEAT_PAD * RPB * 2 + 1024)

__device__ unsigned long long g_keys[N_GATES * 1024];  // zero-init at load
__device__ int g_idx[N_GATES * 1024];
__device__ int g_cnt[2];              // [0]=layer1 live count, [1]=layer2
__device__ int4 g_list1[2048];        // (a, b, dest, isOr), t-ordered
__device__ int4 g_list2[2048];

struct AmDesc {
  const float* w[N_GATES];
  const float* g[N_GATES];
  int din[N_GATES];
  int dout[N_GATES];
  int colTiles[N_GATES];
  int jobEnd[N_GATES];
};

__device__ __forceinline__ unsigned sortable(float f) {
  unsigned u = __float_as_uint(f);
  return (u & 0x80000000u) ? ~u : (u | 0x80000000u);
}

__global__ void argmax_partial_kernel(AmDesc d) {
  int job = blockIdx.x;
  int gi = 0;
  while (gi < N_GATES - 1 && job >= d.jobEnd[gi]) gi++;
  int base = gi ? d.jobEnd[gi - 1] : 0;
  int local = job - base;
  int ct = d.colTiles[gi];
  int rowChunk = local / ct;
  int colTile = local - rowChunk * ct;
  int dout = d.dout[gi];
  int col = colTile * 256 + threadIdx.x;
  const float* __restrict__ wp = d.w[gi] + col;
  const float* __restrict__ gp = d.g[gi] + col;
  int r0 = rowChunk * CHUNK;
  int r1 = min(r0 + CHUNK, d.din[gi]);
  float best = -CUDART_INF_F;
  int bi = r0;
#pragma unroll 4
  for (int r = r0; r < r1; r++) {
    float v = __ldg(wp + (long)r * dout) + __ldg(gp + (long)r * dout);
    if (v > best) { best = v; bi = r; }  // strict '>': first index on ties
  }
  unsigned long long key =
      ((unsigned long long)sortable(best) << 32) |
      (unsigned long long)(0xFFFFFFFFu - (unsigned)bi);
  atomicMax(&g_keys[gi * 1024 + col], key);
}

// ---- finalize: extract + liveness + deterministic compaction, ONE block ----
__global__ __launch_bounds__(FNT) void finalize_kernel() {
  __shared__ unsigned char live[5122];
  __shared__ int warpsum[32];
  const int tid = threadIdx.x;
  const int lane = tid & 31, warp = tid >> 5;

  // zero liveness flags (shared; no cross-call state)
  for (int i = tid; i < 5122; i += FNT) live[i] = 0;

  // extract argmax indices; self-clean keys for the next graph replay
  for (int i = tid; i < N_GATES * 1024; i += FNT) {
    unsigned long long k = g_keys[i];
    g_idx[i] = (int)(0xFFFFFFFFu - (unsigned)(k & 0xFFFFFFFFull));
    g_keys[i] = 0ull;
  }
  __syncthreads();

  // mark features referenced by layer 3 (all 1024 of its gates are live)
  for (int i = tid; i < 2048; i += FNT) {
    int arr = i >> 9, j = i & 511;
    live[g_idx[(8 + arr) * 1024 + j]] = 1;
  }
  __syncthreads();

  // ---- layers 2 then 1: flag live gates, mark inputs, compact in t-order ----
#pragma unroll
  for (int l = 1; l >= 0; l--) {
    const int fbase = l ? 3074 : 1026;
    const int ibase = l ? 4 * 1024 : 0;
    int4* __restrict__ lst = l ? g_list2 : g_list1;

    int fl[2];
    int4 ent[2];
#pragma unroll
    for (int u = 0; u < 2; u++) {
      int t = tid * 2 + u;  // 0..2047
      int isOr = t >> 10, j = t & 1023;
      int f = live[fbase + t];
      fl[u] = f;
      if (f) {
        int a = g_idx[ibase + (isOr ? 2 : 0) * 1024 + j];
        int b = g_idx[ibase + (isOr ? 3 : 1) * 1024 + j];
        ent[u] = make_int4(a, b, fbase + t, isOr);
        if (l) { live[a] = 1; live[b] = 1; }  // inputs are < 3074: no clash
      }
    }
    // block-wide exclusive scan over 2048 flags (2 per thread)
    int tsum = fl[0] + fl[1];
    int v = tsum;
#pragma unroll
    for (int o = 1; o < 32; o <<= 1) {
      int n = __shfl_up_sync(0xffffffffu, v, o);
      if (lane >= o) v += n;
    }
    if (lane == 31) warpsum[warp] = v;
    __syncthreads();
    if (warp == 0) {
      int w = warpsum[lane];
#pragma unroll
      for (int o = 1; o < 32; o <<= 1) {
        int n = __shfl_up_sync(0xffffffffu, w, o);
        if (lane >= o) w += n;
      }
      warpsum[lane] = w;  // inclusive warp totals
    }
    __syncthreads();
    int base = (warp ? warpsum[warp - 1] : 0) + (v - tsum);
    if (fl[0]) lst[base] = ent[0];
    if (fl[1]) lst[base + fl[0]] = ent[1];
    if (tid == 0) g_cnt[l] = warpsum[31];
    __syncthreads();  // warpsum reuse + live[] marks visible for next layer
  }
}

// ---------------- eval ----------------
// h transposed: feature f -> 8 halves (rows 0..7) at 16B granule sm + f*4.

struct H8 { __half2 p0, p1, p2, p3; };

__device__ __forceinline__ H8 ld_feat(const float* sm, int f) {
  float4 v = *(const float4*)(sm + f * 4);
  H8 h;
  h.p0 = *(__half2*)&v.x; h.p1 = *(__half2*)&v.y;
  h.p2 = *(__half2*)&v.z; h.p3 = *(__half2*)&v.w;
  return h;
}
__device__ __forceinline__ void st_feat(float* sm, int f, H8 h) {
  float4 v;
  *(__half2*)&v.x = h.p0; *(__half2*)&v.y = h.p1;
  *(__half2*)&v.z = h.p2; *(__half2*)&v.w = h.p3;
  *(float4*)(sm + f * 4) = v;
}

__device__ __forceinline__ H8 gate_op(H8 a, H8 b, int isOr) {
  H8 o;
  if (!isOr) {
    o.p0 = __hmul2(a.p0, b.p0); o.p1 = __hmul2(a.p1, b.p1);
    o.p2 = __hmul2(a.p2, b.p2); o.p3 = __hmul2(a.p3, b.p3);
  } else {
    const __half2 one = __float2half2_rn(1.0f);
    o.p0 = __hfma2(b.p0, __hsub2(one, a.p0), a.p0);
    o.p1 = __hfma2(b.p1, __hsub2(one, a.p1), a.p1);
    o.p2 = __hfma2(b.p2, __hsub2(one, a.p2), a.p2);
    o.p3 = __hfma2(b.p3, __hsub2(one, a.p3), a.p3);
  }
  return o;
}

__global__ __launch_bounds__(NT, 2) void eval_kernel(
    const float* __restrict__ x,
    const float* __restrict__ lin_w,
    float* __restrict__ out) {
  extern __shared__ float sm[];
  __half* sm_h = (__half*)sm;
  float* sm_red = sm + NFEAT_PAD * RPB / 2;
  const int tid = threadIdx.x;
  const long row0 = (long)blockIdx.x * RPB;

  const int n1 = g_cnt[0];
  const int n2 = g_cnt[1];

  // ---- build h1 = [x, 1-x, 1, 0] via staged transpose ----
  // stage 8 rows x 512 floats (16KB) coalesced into the feature-3074+ slots
  // (only overwritten by layer 2, after this region is dead)
  {
    float* stg = sm + 12296;
    const float4* xg = (const float4*)(x + row0 * 512);
    ((float4*)stg)[tid] = __ldg(xg + tid);
    __syncthreads();
    int c = tid & 511;
    int neg = tid >> 9;
    H8 h;
    float2 f;
#pragma unroll
    for (int p = 0; p < 4; p++) {
      f.x = stg[(2 * p + 0) * 512 + c];
      f.y = stg[(2 * p + 1) * 512 + c];
      if (neg) { f.x = 1.0f - f.x; f.y = 1.0f - f.y; }
      __half2 hv = __floats2half2_rn(f.x, f.y);
      if (p == 0) h.p0 = hv; else if (p == 1) h.p1 = hv;
      else if (p == 2) h.p2 = hv; else h.p3 = hv;
    }
    st_feat(sm, neg * 512 + c, h);
    if (tid < RPB) {
      sm_h[1024 * 8 + tid] = __float2half_rn(1.0f);
      sm_h[1025 * 8 + tid] = __float2half_rn(0.0f);
    }
    __syncthreads();
  }

  // ---- layer 1 (live gates only, t-ordered => sequential stores) ----
  for (int t = tid; t < n1; t += NT) {
    int4 e = __ldg((const int4*)g_list1 + t);
    H8 va = ld_feat(sm, e.x);
    H8 vb = ld_feat(sm, e.y);
    st_feat(sm, e.z, gate_op(va, vb, e.w));
  }
  __syncthreads();

  // ---- layer 2 (live gates only) ----
  for (int t = tid; t < n2; t += NT) {
    int4 e = __ldg((const int4*)g_list2 + t);
    H8 va = ld_feat(sm, e.x);
    H8 vb = ld_feat(sm, e.y);
    st_feat(sm, e.z, gate_op(va, vb, e.w));
  }
  __syncthreads();

  // ---- layer 3 fused with lin_w dot ----
  {
    const int* __restrict__ ib = g_idx + 8 * 1024;
    float acc[8];
#pragma unroll
    for (int k = 0; k < 8; k++) acc[k] = 0.0f;
    {
      int t = tid;  // single trip (1024 items, NT=1024)
      int isOr = t >> 9;
      int j = t & 511;
      int a = __ldg(ib + (isOr ? 2 : 0) * 1024 + j);
      int b = __ldg(ib + (isOr ? 3 : 1) * 1024 + j);
      float w = __ldg(lin_w + isOr * 512 + j);
      H8 va = ld_feat(sm, a);
      H8 vb = ld_feat(sm, b);
      H8 o = gate_op(va, vb, isOr);
      float2 f0 = __half22float2(o.p0);
      float2 f1 = __half22float2(o.p1);
      float2 f2 = __half22float2(o.p2);
      float2 f3 = __half22float2(o.p3);
      acc[0] += w * f0.x; acc[1] += w * f0.y;
      acc[2] += w * f1.x; acc[3] += w * f1.y;
      acc[4] += w * f2.x; acc[5] += w * f2.y;
      acc[6] += w * f3.x; acc[7] += w * f3.y;
    }
#pragma unroll
    for (int off = 16; off; off >>= 1)
#pragma unroll
      for (int k = 0; k < 8; k++)
        acc[k] += __shfl_down_sync(0xffffffffu, acc[k], off);
    int warp = tid >> 5, lane = tid & 31;
    if (lane == 0)
#pragma unroll
      for (int k = 0; k < 8; k++) sm_red[warp * 8 + k] = acc[k];
    __syncthreads();
    if (tid < 8) {
      float s = 0.0f;
#pragma unroll
      for (int w = 0; w < NT / 32; w++) s += sm_red[w * 8 + tid];
      out[row0 + tid] = s;
    }
  }
}

// ============================================================================

extern "C" void kernel_launch(void* const* d_in, const int* in_sizes, int n_in,
                              void* d_out, int out_size) {
  const int S_L[3] = {1026 * 1024, 3074 * 1024, 5122 * 512};
  int lstart[3] = {-1, -1, -1};
  int xi = -1, lwi = -1;
  for (int i = 0; i < n_in; i++) {
    int s = in_sizes[i];
    if (s == 32768 * 512) { if (xi < 0) xi = i; }
    else if (s == 1024) { if (lwi < 0) lwi = i; }
    else {
      for (int l = 0; l < 3; l++)
        if (s == S_L[l] && lstart[l] < 0) { lstart[l] = i; break; }
    }
  }

  AmDesc d;
  const int din[3] = {1026, 3074, 5122};
  const int dout[3] = {1024, 1024, 512};
  int cum = 0;
  for (int l = 0; l < 3; l++) {
    for (int t = 0; t < 4; t++) {
      int gi = l * 4 + t;
      d.w[gi] = (const float*)d_in[lstart[l] + t];
      d.g[gi] = (const float*)d_in[lstart[l] + 4 + t];
      d.din[gi] = din[l];
      d.dout[gi] = dout[l];
      int ct = dout[l] / 256;
      d.colTiles[gi] = ct;
      int rc = (din[l] + CHUNK - 1) / CHUNK;
      cum += rc * ct;
      d.jobEnd[gi] = cum;
    }
  }

  argmax_partial_kernel<<<cum, 256>>>(d);
  finalize_kernel<<<1, FNT>>>();

  cudaFuncSetAttribute(eval_kernel, cudaFuncAttributeMaxDynamicSharedMemorySize,
                       EVAL_SMEM);
  eval_kernel<<<32768 / RPB, NT, EVAL_SMEM>>>(
      (const float*)d_in[xi], (const float*)d_in[lwi], (float*)d_out);
}